// round 6
// baseline (speedup 1.0000x reference)
#include <cuda_runtime.h>
#include <cstdint>

#define B_DIM  32768
#define IN_DIM 1024
#define U_DIM  1024
#define E_DIM  8

#define BM 128
#define BN 128
#define BK 32
#define THREADS 256
#define NITER 256               // 32 kc * 8 e
#define NBSTAGE 6

// smem layout in floats
#define AROW 36                 // 32 + 4 pad: A frag LDS conflict-free
#define BROW 136                // 128 + 8 pad: B frag LDS conflict-free
#define A_STAGE_F (128 * AROW)  // 4608
#define B_STAGE_F (32 * BROW)   // 4352
#define OFF_GATE 0              // 128*8
#define OFF_BETA 1024           // 8*128
#define OFF_A    2048
#define OFF_B    (OFF_A + 2 * A_STAGE_F)          // 11264
#define SMEM_FLOATS (OFF_B + NBSTAGE * B_STAGE_F) // 37376
#define SMEM_BYTES (SMEM_FLOATS * 4)              // 149504

__device__ float g_alphaR[(size_t)E_DIM * IN_DIM * U_DIM];   // rna-rounded alpha

__device__ __forceinline__ uint32_t smem_u32(const void* p) {
    uint32_t a;
    asm("{ .reg .u64 t; cvta.to.shared.u64 t, %1; cvt.u32.u64 %0, t; }" : "=r"(a) : "l"(p));
    return a;
}
__device__ __forceinline__ uint32_t f2tf32(float f) {
    uint32_t r; asm("cvt.rna.tf32.f32 %0, %1;" : "=r"(r) : "f"(f)); return r;
}
__device__ __forceinline__ void cp16(uint32_t dst, const void* src) {
    asm volatile("cp.async.cg.shared.global [%0], [%1], 16;" :: "r"(dst), "l"(src));
}
#define CP_COMMIT() asm volatile("cp.async.commit_group;" ::: "memory")
#define CP_WAIT2()  asm volatile("cp.async.wait_group 2;" ::: "memory")

__device__ __forceinline__ void mma_tf32(float c[4],
                                         uint32_t a0, uint32_t a1, uint32_t a2, uint32_t a3,
                                         uint32_t b0, uint32_t b1) {
    asm volatile(
        "mma.sync.aligned.m16n8k8.row.col.f32.tf32.tf32.f32 "
        "{%0,%1,%2,%3}, {%4,%5,%6,%7}, {%8,%9}, {%0,%1,%2,%3};\n"
        : "+f"(c[0]), "+f"(c[1]), "+f"(c[2]), "+f"(c[3])
        : "r"(a0), "r"(a1), "r"(a2), "r"(a3), "r"(b0), "r"(b1));
}

// ---------------- prologue: rna-round alpha into scratch ----------------
__global__ void round_alpha(const float* __restrict__ alpha) {
    const size_t idx = ((size_t)blockIdx.x * 256 + threadIdx.x) * 4;
    float4 v = *reinterpret_cast<const float4*>(alpha + idx);
    float4 r;
    r.x = __uint_as_float(f2tf32(v.x));
    r.y = __uint_as_float(f2tf32(v.y));
    r.z = __uint_as_float(f2tf32(v.z));
    r.w = __uint_as_float(f2tf32(v.w));
    *reinterpret_cast<float4*>(g_alphaR + idx) = r;
}

// ---------------- main kernel ----------------
__global__ __launch_bounds__(THREADS, 1)
void moe_kernel(const float* __restrict__ x,
                const float* __restrict__ gate,
                const float* __restrict__ beta,
                float* __restrict__ out)
{
    extern __shared__ float sm[];
    float* gate_sh = sm + OFF_GATE;
    float* beta_sh = sm + OFF_BETA;
    const uint32_t sbase = smem_u32(sm);
    const uint32_t aA = sbase + OFF_A * 4;
    const uint32_t aB = sbase + OFF_B * 4;

    const int tid  = threadIdx.x;
    const int wid  = tid >> 5;
    const int lane = tid & 31;
    const int warp_m = wid & 1;       // 2-way split over m (64 rows each)
    const int warp_n = wid >> 1;      // 4-way split over n (32 cols each)
    const int g  = lane >> 2;
    const int tg = lane & 3;
    const int mbase = blockIdx.y * BM;
    const int ubase = blockIdx.x * BN;

    // stage gate (128x8) and beta (8x128) tiles
    {
        const int idx = tid * 4;
        float4 gv = *reinterpret_cast<const float4*>(gate + (size_t)mbase * E_DIM + idx);
        *reinterpret_cast<float4*>(gate_sh + idx) = gv;
        const int e = idx >> 7, c = idx & 127;
        float4 bv = *reinterpret_cast<const float4*>(beta + (size_t)e * U_DIM + ubase + c);
        *reinterpret_cast<float4*>(beta_sh + idx) = bv;
    }

    // cp.async geometry
    const int a_row  = tid >> 1;          // 0..127
    const int a_half = (tid & 1) * 16;    // k offset
    const int b_k    = tid >> 3;          // 0..31
    const int b_c    = tid & 7;           // 16B chunk base

    auto issueA = [&](int kc) {
        const int st = kc & 1;
        const uint32_t dst = aA + st * (A_STAGE_F * 4) + a_row * (AROW * 4) + a_half * 4;
        const float* src = x + (size_t)(mbase + a_row) * IN_DIM + kc * BK + a_half;
#pragma unroll
        for (int j = 0; j < 4; ++j) cp16(dst + j * 16, src + j * 4);
    };
    auto issueB = [&](int it, int st) {
        const int kc = it >> 3, e = it & 7;
        const uint32_t dst = aB + st * (B_STAGE_F * 4) + b_k * (BROW * 4) + b_c * 16;
        const float* src = g_alphaR + (size_t)e * (IN_DIM * U_DIM)
                         + (size_t)(kc * BK + b_k) * U_DIM + ubase + b_c * 4;
#pragma unroll
        for (int j = 0; j < 4; ++j) cp16(dst + j * 128, src + j * 32);
    };

    float Ar[4][4][4];     // [ks][mm][frag] unscaled x fragments, cached per kc
    float acc[4][4][4];    // [mm][nn][frag]
#pragma unroll
    for (int i = 0; i < 4; ++i)
#pragma unroll
        for (int j = 0; j < 4; ++j)
#pragma unroll
            for (int k = 0; k < 4; ++k) acc[i][j][k] = 0.f;

    // compute one (kc, e) chunk from B stage st
    auto compute = [&](int i, int st) {
        const int kc = i >> 3, e = i & 7;
        const float* Bs = sm + OFF_B + st * B_STAGE_F;

        if (e == 0) {
            const float* As = sm + OFF_A + (kc & 1) * A_STAGE_F;
#pragma unroll
            for (int ks = 0; ks < 4; ++ks)
#pragma unroll
                for (int mm = 0; mm < 4; ++mm) {
                    const int r0 = warp_m * 64 + mm * 16 + g;
                    const int k0 = ks * 8 + tg;
                    Ar[ks][mm][0] = As[r0 * AROW + k0];
                    Ar[ks][mm][1] = As[(r0 + 8) * AROW + k0];
                    Ar[ks][mm][2] = As[r0 * AROW + k0 + 4];
                    Ar[ks][mm][3] = As[(r0 + 8) * AROW + k0 + 4];
                }
        }

        float gs0[4], gs1[4];
#pragma unroll
        for (int mm = 0; mm < 4; ++mm) {
            const int r0 = warp_m * 64 + mm * 16 + g;
            gs0[mm] = gate_sh[r0 * E_DIM + e];
            gs1[mm] = gate_sh[(r0 + 8) * E_DIM + e];
        }

#pragma unroll
        for (int ks = 0; ks < 4; ++ks) {
            uint32_t b0[4], b1[4];
#pragma unroll
            for (int nn = 0; nn < 4; ++nn) {
                const int n = warp_n * 32 + nn * 8 + g;
                const int k = ks * 8 + tg;
                b0[nn] = __float_as_uint(Bs[k * BROW + n]);
                b1[nn] = __float_as_uint(Bs[(k + 4) * BROW + n]);
            }
#pragma unroll
            for (int mm = 0; mm < 4; ++mm) {
                const uint32_t a0 = __float_as_uint(Ar[ks][mm][0] * gs0[mm]);
                const uint32_t a1 = __float_as_uint(Ar[ks][mm][1] * gs1[mm]);
                const uint32_t a2 = __float_as_uint(Ar[ks][mm][2] * gs0[mm]);
                const uint32_t a3 = __float_as_uint(Ar[ks][mm][3] * gs1[mm]);
#pragma unroll
                for (int nn = 0; nn < 4; ++nn)
                    mma_tf32(acc[mm][nn], a0, a1, a2, a3, b0[nn], b1[nn]);
            }
        }
    };

    // prologue: groups for i = 0..3 into B stages 0..3 (A kc=0 with group 0)
    issueA(0); issueB(0, 0); CP_COMMIT();
    issueB(1, 1);            CP_COMMIT();
    issueB(2, 2);            CP_COMMIT();
    issueB(3, 3);            CP_COMMIT();
    CP_WAIT2();              // groups 0,1 complete
    __syncthreads();

    int s_c = 0;   // consume stage for i0 = 2j   (even, cycles 0,2,4)
    int s_w = 4;   // write stage for i4 = 2j+4

    for (int j = 0; j < NITER / 2; ++j) {
        const int i0 = 2 * j;
        const int i4 = i0 + 4, i5 = i0 + 5;
        if (i4 < NITER) {
            issueB(i4, s_w);
            if ((i4 & 7) == 0) issueA(i4 >> 3);
        }
        CP_COMMIT();
        if (i5 < NITER) issueB(i5, s_w + 1);
        CP_COMMIT();

        compute(i0, s_c);
        compute(i0 + 1, s_c + 1);

        CP_WAIT2();            // groups up through i0+3 complete
        __syncthreads();

        s_c += 2; if (s_c == NBSTAGE) s_c = 0;
        s_w += 2; if (s_w == NBSTAGE) s_w = 0;
    }

    // epilogue: out = acc + sum_e gate[b,e] * beta[e,u]
#pragma unroll
    for (int mm = 0; mm < 4; ++mm) {
        const int row0 = warp_m * 64 + mm * 16 + g;
        const int row1 = row0 + 8;
        float ge0[E_DIM], ge1[E_DIM];
#pragma unroll
        for (int e = 0; e < E_DIM; ++e) {
            ge0[e] = gate_sh[row0 * E_DIM + e];
            ge1[e] = gate_sh[row1 * E_DIM + e];
        }
#pragma unroll
        for (int nn = 0; nn < 4; ++nn) {
            const int c = warp_n * 32 + nn * 8 + 2 * tg;
            float b00 = 0.f, b01 = 0.f, b10 = 0.f, b11 = 0.f;
#pragma unroll
            for (int e = 0; e < E_DIM; ++e) {
                const float be0 = beta_sh[e * BN + c];
                const float be1 = beta_sh[e * BN + c + 1];
                b00 += ge0[e] * be0;  b01 += ge0[e] * be1;
                b10 += ge1[e] * be0;  b11 += ge1[e] * be1;
            }
            float2 v0 = make_float2(acc[mm][nn][0] + b00, acc[mm][nn][1] + b01);
            float2 v1 = make_float2(acc[mm][nn][2] + b10, acc[mm][nn][3] + b11);
            *reinterpret_cast<float2*>(out + (size_t)(mbase + row0) * U_DIM + ubase + c) = v0;
            *reinterpret_cast<float2*>(out + (size_t)(mbase + row1) * U_DIM + ubase + c) = v1;
        }
    }
}

extern "C" void kernel_launch(void* const* d_in, const int* in_sizes, int n_in,
                              void* d_out, int out_size)
{
    const float* x     = (const float*)d_in[0];
    const float* gate  = (const float*)d_in[1];
    const float* alpha = (const float*)d_in[2];
    const float* beta  = (const float*)d_in[3];
    float* out         = (float*)d_out;

    round_alpha<<<(E_DIM * IN_DIM * U_DIM) / (256 * 4), 256>>>(alpha);

    static bool attr_set = false;
    if (!attr_set) {
        cudaFuncSetAttribute(moe_kernel, cudaFuncAttributeMaxDynamicSharedMemorySize, SMEM_BYTES);
        attr_set = true;
    }
    moe_kernel<<<dim3(U_DIM / BN, B_DIM / BM), THREADS, SMEM_BYTES>>>(x, gate, beta, out);
}

// round 8
// speedup vs baseline: 1.0404x; 1.0404x over previous
#include <cuda_runtime.h>
#include <cstdint>

#define B_DIM  32768
#define IN_DIM 1024
#define U_DIM  1024
#define E_DIM  8

#define BM 64
#define BN 128
#define BK 32
#define THREADS 256
#define NITER 256               // 32 kc * 8 e

// smem layout in floats
#define AROW 36                 // 32 + 4 pad: A frag LDS conflict-free
#define BROW 136                // 128 + 8 pad: B frag LDS conflict-free
#define A_STAGE_F (BM * AROW)   // 2304
#define B_STAGE_F (32 * BROW)   // 4352
#define OFF_GATE 0              // 64*8 = 512
#define OFF_BETA 512            // 8*128 = 1024
#define OFF_A    1536
#define OFF_B    (OFF_A + 2 * A_STAGE_F)        // 6144
#define SMEM_FLOATS (OFF_B + 3 * B_STAGE_F)     // 19200
#define SMEM_BYTES (SMEM_FLOATS * 4)            // 76800

__device__ float g_alphaR[(size_t)E_DIM * IN_DIM * U_DIM];   // rna-rounded alpha

__device__ __forceinline__ uint32_t smem_u32(const void* p) {
    uint32_t a;
    asm("{ .reg .u64 t; cvta.to.shared.u64 t, %1; cvt.u32.u64 %0, t; }" : "=r"(a) : "l"(p));
    return a;
}
__device__ __forceinline__ uint32_t f2tf32(float f) {
    uint32_t r; asm("cvt.rna.tf32.f32 %0, %1;" : "=r"(r) : "f"(f)); return r;
}
__device__ __forceinline__ void cp16(uint32_t dst, const void* src) {
    asm volatile("cp.async.cg.shared.global [%0], [%1], 16;" :: "r"(dst), "l"(src));
}
#define CP_COMMIT() asm volatile("cp.async.commit_group;" ::: "memory")
#define CP_WAIT1()  asm volatile("cp.async.wait_group 1;" ::: "memory")

__device__ __forceinline__ void mma_tf32(float c[4],
                                         uint32_t a0, uint32_t a1, uint32_t a2, uint32_t a3,
                                         uint32_t b0, uint32_t b1) {
    asm volatile(
        "mma.sync.aligned.m16n8k8.row.col.f32.tf32.tf32.f32 "
        "{%0,%1,%2,%3}, {%4,%5,%6,%7}, {%8,%9}, {%0,%1,%2,%3};\n"
        : "+f"(c[0]), "+f"(c[1]), "+f"(c[2]), "+f"(c[3])
        : "r"(a0), "r"(a1), "r"(a2), "r"(a3), "r"(b0), "r"(b1));
}

// ---------------- prologue: rna-round alpha into scratch ----------------
__global__ void round_alpha(const float* __restrict__ alpha) {
    const size_t idx = ((size_t)blockIdx.x * 256 + threadIdx.x) * 4;
    float4 v = *reinterpret_cast<const float4*>(alpha + idx);
    float4 r;
    r.x = __uint_as_float(f2tf32(v.x));
    r.y = __uint_as_float(f2tf32(v.y));
    r.z = __uint_as_float(f2tf32(v.z));
    r.w = __uint_as_float(f2tf32(v.w));
    *reinterpret_cast<float4*>(g_alphaR + idx) = r;
}

// ---------------- main kernel ----------------
__global__ __launch_bounds__(THREADS, 2)
void moe_kernel(const float* __restrict__ x,
                const float* __restrict__ gate,
                const float* __restrict__ beta,
                float* __restrict__ out)
{
    extern __shared__ float sm[];
    float* gate_sh = sm + OFF_GATE;
    float* beta_sh = sm + OFF_BETA;
    const uint32_t sbase = smem_u32(sm);
    const uint32_t aA = sbase + OFF_A * 4;
    const uint32_t aB = sbase + OFF_B * 4;

    const int tid  = threadIdx.x;
    const int wid  = tid >> 5;
    const int lane = tid & 31;
    const int warp_m = wid & 1;       // 2-way over m (32 rows each)
    const int warp_n = wid >> 1;      // 4-way over n (32 cols each)
    const int g  = lane >> 2;
    const int tg = lane & 3;
    const int mbase = blockIdx.y * BM;
    const int ubase = blockIdx.x * BN;

    // stage gate (64x8) and beta (8x128) tiles
    if (tid < 128) {
        const int idx = tid * 4;
        float4 gv = *reinterpret_cast<const float4*>(gate + (size_t)mbase * E_DIM + idx);
        *reinterpret_cast<float4*>(gate_sh + idx) = gv;
    }
    {
        const int idx = tid * 4;
        const int e = idx >> 7, c = idx & 127;
        float4 bv = *reinterpret_cast<const float4*>(beta + (size_t)e * U_DIM + ubase + c);
        *reinterpret_cast<float4*>(beta_sh + idx) = bv;
    }

    // cp.async geometry
    const int a_row = tid >> 2;           // 0..63
    const int a_kq  = (tid & 3) * 8;      // k offset (8 floats = 2x cp16)
    const int b_k   = tid >> 3;           // 0..31
    const int b_c   = tid & 7;            // 16B chunk base

    auto issueA = [&](int kc) {
        const int st = kc & 1;
        const uint32_t dst = aA + st * (A_STAGE_F * 4) + a_row * (AROW * 4) + a_kq * 4;
        const float* src = x + (size_t)(mbase + a_row) * IN_DIM + kc * BK + a_kq;
        cp16(dst,      src);
        cp16(dst + 16, src + 4);
    };
    auto issueB = [&](int it) {
        const int st = it % 3;
        const int kc = it >> 3, e = it & 7;
        const uint32_t dst = aB + st * (B_STAGE_F * 4) + b_k * (BROW * 4) + b_c * 16;
        const float* src = g_alphaR + (size_t)e * (IN_DIM * U_DIM)
                         + (size_t)(kc * BK + b_k) * U_DIM + ubase + b_c * 4;
#pragma unroll
        for (int j = 0; j < 4; ++j) cp16(dst + j * 128, src + j * 32);
    };

    // prologue: groups for iters 0 and 1
    issueA(0); issueB(0); CP_COMMIT();
    issueB(1);            CP_COMMIT();
    CP_WAIT1();
    __syncthreads();

    float Ar[4][2][4];     // [ks][mm][frag] unscaled x fragments, cached per kc
    float acc[2][4][4];    // [mm][nn][frag]
#pragma unroll
    for (int i = 0; i < 2; ++i)
#pragma unroll
        for (int j = 0; j < 4; ++j)
#pragma unroll
            for (int k = 0; k < 4; ++k) acc[i][j][k] = 0.f;

    for (int i = 0; i < NITER; ++i) {
        const int i2 = i + 2;
        if (i2 < NITER) {
            issueB(i2);
            if ((i2 & 7) == 0) issueA(i2 >> 3);
        }
        CP_COMMIT();

        const int kc = i >> 3, e = i & 7;
        const float* Bs = sm + OFF_B + (i % 3) * B_STAGE_F;

        if (e == 0) {
            const float* As = sm + OFF_A + (kc & 1) * A_STAGE_F;
#pragma unroll
            for (int ks = 0; ks < 4; ++ks)
#pragma unroll
                for (int mm = 0; mm < 2; ++mm) {
                    const int r0 = warp_m * 32 + mm * 16 + g;
                    const int k0 = ks * 8 + tg;
                    Ar[ks][mm][0] = As[r0 * AROW + k0];
                    Ar[ks][mm][1] = As[(r0 + 8) * AROW + k0];
                    Ar[ks][mm][2] = As[r0 * AROW + k0 + 4];
                    Ar[ks][mm][3] = As[(r0 + 8) * AROW + k0 + 4];
                }
        }

        // per-expert gate scales for this lane's rows
        float gs0[2], gs1[2];
#pragma unroll
        for (int mm = 0; mm < 2; ++mm) {
            const int r0 = warp_m * 32 + mm * 16 + g;
            gs0[mm] = gate_sh[r0 * E_DIM + e];
            gs1[mm] = gate_sh[(r0 + 8) * E_DIM + e];
        }

#pragma unroll
        for (int ks = 0; ks < 4; ++ks) {
            uint32_t b0[4], b1[4];
#pragma unroll
            for (int nn = 0; nn < 4; ++nn) {
                const int n = warp_n * 32 + nn * 8 + g;
                const int k = ks * 8 + tg;
                b0[nn] = __float_as_uint(Bs[k * BROW + n]);
                b1[nn] = __float_as_uint(Bs[(k + 4) * BROW + n]);
            }
#pragma unroll
            for (int mm = 0; mm < 2; ++mm) {
                const uint32_t a0 = __float_as_uint(Ar[ks][mm][0] * gs0[mm]);
                const uint32_t a1 = __float_as_uint(Ar[ks][mm][1] * gs1[mm]);
                const uint32_t a2 = __float_as_uint(Ar[ks][mm][2] * gs0[mm]);
                const uint32_t a3 = __float_as_uint(Ar[ks][mm][3] * gs1[mm]);
#pragma unroll
                for (int nn = 0; nn < 4; ++nn)
                    mma_tf32(acc[mm][nn], a0, a1, a2, a3, b0[nn], b1[nn]);
            }
        }

        CP_WAIT1();
        __syncthreads();
    }

    // epilogue: out = acc + sum_e gate[b,e] * beta[e,u]
#pragma unroll
    for (int mm = 0; mm < 2; ++mm) {
        const int row0 = warp_m * 32 + mm * 16 + g;
        const int row1 = row0 + 8;
        float ge0[E_DIM], ge1[E_DIM];
#pragma unroll
        for (int e = 0; e < E_DIM; ++e) {
            ge0[e] = gate_sh[row0 * E_DIM + e];
            ge1[e] = gate_sh[row1 * E_DIM + e];
        }
#pragma unroll
        for (int nn = 0; nn < 4; ++nn) {
            const int c = warp_n * 32 + nn * 8 + 2 * tg;
            float b00 = 0.f, b01 = 0.f, b10 = 0.f, b11 = 0.f;
#pragma unroll
            for (int e = 0; e < E_DIM; ++e) {
                const float be0 = beta_sh[e * BN + c];
                const float be1 = beta_sh[e * BN + c + 1];
                b00 += ge0[e] * be0;  b01 += ge0[e] * be1;
                b10 += ge1[e] * be0;  b11 += ge1[e] * be1;
            }
            float2 v0 = make_float2(acc[mm][nn][0] + b00, acc[mm][nn][1] + b01);
            float2 v1 = make_float2(acc[mm][nn][2] + b10, acc[mm][nn][3] + b11);
            *reinterpret_cast<float2*>(out + (size_t)(mbase + row0) * U_DIM + ubase + c) = v0;
            *reinterpret_cast<float2*>(out + (size_t)(mbase + row1) * U_DIM + ubase + c) = v1;
        }
    }
}

extern "C" void kernel_launch(void* const* d_in, const int* in_sizes, int n_in,
                              void* d_out, int out_size)
{
    const float* x     = (const float*)d_in[0];
    const float* gate  = (const float*)d_in[1];
    const float* alpha = (const float*)d_in[2];
    const float* beta  = (const float*)d_in[3];
    float* out         = (float*)d_out;

    round_alpha<<<(E_DIM * IN_DIM * U_DIM) / (256 * 4), 256>>>(alpha);

    static bool attr_set = false;
    if (!attr_set) {
        cudaFuncSetAttribute(moe_kernel, cudaFuncAttributeMaxDynamicSharedMemorySize, SMEM_BYTES);
        attr_set = true;
    }
    moe_kernel<<<dim3(U_DIM / BN, B_DIM / BM), THREADS, SMEM_BYTES>>>(x, gate, beta, out);
}

// round 9
// speedup vs baseline: 1.6231x; 1.5601x over previous
#include <cuda_runtime.h>
#include <cstdint>

#define B_DIM  32768
#define IN_DIM 1024
#define U_DIM  1024
#define E_DIM  8

#define BM 128
#define BN 128
#define BK 32
#define THREADS 512
#define NITER 256               // 32 kc * 8 e

// smem layout in floats
#define AROW 36                 // 32 + 4 pad: A frag LDS conflict-free
#define BROW 136                // 128 + 8 pad: B frag LDS conflict-free
#define A_STAGE_F (BM * AROW)   // 4608
#define B_STAGE_F (32 * BROW)   // 4352
#define OFF_GATE 0              // 128*8 = 1024
#define OFF_BETA 1024           // 8*128 = 1024
#define OFF_A    2048
#define OFF_B    (OFF_A + 2 * A_STAGE_F)        // 11264
#define SMEM_FLOATS (OFF_B + 4 * B_STAGE_F)     // 28672
#define SMEM_BYTES (SMEM_FLOATS * 4)            // 114688

__device__ float g_alphaR[(size_t)E_DIM * IN_DIM * U_DIM];   // rna-rounded alpha

__device__ __forceinline__ uint32_t smem_u32(const void* p) {
    uint32_t a;
    asm("{ .reg .u64 t; cvta.to.shared.u64 t, %1; cvt.u32.u64 %0, t; }" : "=r"(a) : "l"(p));
    return a;
}
__device__ __forceinline__ uint32_t f2tf32(float f) {
    uint32_t r; asm("cvt.rna.tf32.f32 %0, %1;" : "=r"(r) : "f"(f)); return r;
}
__device__ __forceinline__ void cp16(uint32_t dst, const void* src) {
    asm volatile("cp.async.cg.shared.global [%0], [%1], 16;" :: "r"(dst), "l"(src));
}
#define CP_COMMIT() asm volatile("cp.async.commit_group;" ::: "memory")
#define CP_WAIT2()  asm volatile("cp.async.wait_group 2;" ::: "memory")

__device__ __forceinline__ void mma_tf32(float c[4],
                                         uint32_t a0, uint32_t a1, uint32_t a2, uint32_t a3,
                                         uint32_t b0, uint32_t b1) {
    asm volatile(
        "mma.sync.aligned.m16n8k8.row.col.f32.tf32.tf32.f32 "
        "{%0,%1,%2,%3}, {%4,%5,%6,%7}, {%8,%9}, {%0,%1,%2,%3};\n"
        : "+f"(c[0]), "+f"(c[1]), "+f"(c[2]), "+f"(c[3])
        : "r"(a0), "r"(a1), "r"(a2), "r"(a3), "r"(b0), "r"(b1));
}

// ---------------- prologue: rna-round alpha into scratch ----------------
__global__ void round_alpha(const float* __restrict__ alpha) {
    const size_t idx = ((size_t)blockIdx.x * 256 + threadIdx.x) * 4;
    float4 v = *reinterpret_cast<const float4*>(alpha + idx);
    float4 r;
    r.x = __uint_as_float(f2tf32(v.x));
    r.y = __uint_as_float(f2tf32(v.y));
    r.z = __uint_as_float(f2tf32(v.z));
    r.w = __uint_as_float(f2tf32(v.w));
    *reinterpret_cast<float4*>(g_alphaR + idx) = r;
}

// ---------------- main kernel ----------------
__global__ __launch_bounds__(THREADS, 1)
void moe_kernel(const float* __restrict__ x,
                const float* __restrict__ gate,
                const float* __restrict__ beta,
                float* __restrict__ out)
{
    extern __shared__ float sm[];
    float* gate_sh = sm + OFF_GATE;
    float* beta_sh = sm + OFF_BETA;
    const uint32_t sbase = smem_u32(sm);
    const uint32_t aA = sbase + OFF_A * 4;
    const uint32_t aB = sbase + OFF_B * 4;

    const int tid  = threadIdx.x;
    const int wid  = tid >> 5;
    const int lane = tid & 31;
    const int warp_m = wid & 3;       // 4-way over m (32 rows each)
    const int warp_n = wid >> 2;      // 4-way over n (32 cols each)
    const int g  = lane >> 2;
    const int tg = lane & 3;
    const int mbase = blockIdx.y * BM;
    const int ubase = blockIdx.x * BN;

    // stage gate (128x8) and beta (8x128) tiles
    if (tid < 256) {
        const int idx = tid * 4;
        float4 gv = *reinterpret_cast<const float4*>(gate + (size_t)mbase * E_DIM + idx);
        *reinterpret_cast<float4*>(gate_sh + idx) = gv;
    } else {
        const int idx = (tid - 256) * 4;
        const int e = idx >> 7, c = idx & 127;
        float4 bv = *reinterpret_cast<const float4*>(beta + (size_t)e * U_DIM + ubase + c);
        *reinterpret_cast<float4*>(beta_sh + idx) = bv;
    }

    // cp.async geometry (2x cp16 per thread per tile)
    const int a_row = tid >> 2;           // 0..127
    const int a_kq  = (tid & 3) * 8;      // k offset, 8 floats
    const int b_k   = tid >> 4;           // 0..31
    const int b_cq  = (tid & 15) * 8;     // col offset, 8 floats

    auto issueA = [&](int kc, int st) {
        const uint32_t dst = aA + st * (A_STAGE_F * 4) + a_row * (AROW * 4) + a_kq * 4;
        const float* src = x + (size_t)(mbase + a_row) * IN_DIM + kc * BK + a_kq;
        cp16(dst,      src);
        cp16(dst + 16, src + 4);
    };
    auto issueB = [&](int it, int st) {
        const int kc = it >> 3, e = it & 7;
        const uint32_t dst = aB + st * (B_STAGE_F * 4) + b_k * (BROW * 4) + b_cq * 4;
        const float* src = g_alphaR + (size_t)e * (IN_DIM * U_DIM)
                         + (size_t)(kc * BK + b_k) * U_DIM + ubase + b_cq;
        cp16(dst,      src);
        cp16(dst + 16, src + 4);
    };

    float Ar[4][2][4];     // [ks][mm][frag] unscaled x fragments, cached per kc
    float acc[2][4][4];    // [mm][nn][frag]
#pragma unroll
    for (int i = 0; i < 2; ++i)
#pragma unroll
        for (int j = 0; j < 4; ++j)
#pragma unroll
            for (int k = 0; k < 4; ++k) acc[i][j][k] = 0.f;

    // prologue: groups for chunks 0,1,2 (A kc=0 rides with group 0)
    issueA(0, 0); issueB(0, 0); CP_COMMIT();
    issueB(1, 1);               CP_COMMIT();
    issueB(2, 2);               CP_COMMIT();
    CP_WAIT2();                 // group 0 complete
    __syncthreads();

#pragma unroll 2
    for (int kc = 0; kc < 32; ++kc) {
#pragma unroll
        for (int e = 0; e < E_DIM; ++e) {
            const int i = kc * 8 + e;
            // issue loads for chunk i+3 into stage (e+3)&3 (compile-time)
            if (i + 3 < NITER) {
                issueB(i + 3, (e + 3) & 3);
                if (e == 5) issueA(kc + 1, (kc + 1) & 1);
            }
            CP_COMMIT();

            const float* Bs = sm + OFF_B + (e & 3) * B_STAGE_F;

            if (e == 0) {
                const float* As = sm + OFF_A + (kc & 1) * A_STAGE_F;
#pragma unroll
                for (int ks = 0; ks < 4; ++ks)
#pragma unroll
                    for (int mm = 0; mm < 2; ++mm) {
                        const int r0 = warp_m * 32 + mm * 16 + g;
                        const int k0 = ks * 8 + tg;
                        Ar[ks][mm][0] = As[r0 * AROW + k0];
                        Ar[ks][mm][1] = As[(r0 + 8) * AROW + k0];
                        Ar[ks][mm][2] = As[r0 * AROW + k0 + 4];
                        Ar[ks][mm][3] = As[(r0 + 8) * AROW + k0 + 4];
                    }
            }

            float gs0[2], gs1[2];
#pragma unroll
            for (int mm = 0; mm < 2; ++mm) {
                const int r0 = warp_m * 32 + mm * 16 + g;
                gs0[mm] = gate_sh[r0 * E_DIM + e];
                gs1[mm] = gate_sh[(r0 + 8) * E_DIM + e];
            }

#pragma unroll
            for (int ks = 0; ks < 4; ++ks) {
                uint32_t b0[4], b1[4];
#pragma unroll
                for (int nn = 0; nn < 4; ++nn) {
                    const int n = warp_n * 32 + nn * 8 + g;
                    const int k = ks * 8 + tg;
                    b0[nn] = __float_as_uint(Bs[k * BROW + n]);
                    b1[nn] = __float_as_uint(Bs[(k + 4) * BROW + n]);
                }
#pragma unroll
                for (int mm = 0; mm < 2; ++mm) {
                    const uint32_t a0 = __float_as_uint(Ar[ks][mm][0] * gs0[mm]);
                    const uint32_t a1 = __float_as_uint(Ar[ks][mm][1] * gs1[mm]);
                    const uint32_t a2 = __float_as_uint(Ar[ks][mm][2] * gs0[mm]);
                    const uint32_t a3 = __float_as_uint(Ar[ks][mm][3] * gs1[mm]);
#pragma unroll
                    for (int nn = 0; nn < 4; ++nn)
                        mma_tf32(acc[mm][nn], a0, a1, a2, a3, b0[nn], b1[nn]);
                }
            }

            CP_WAIT2();          // group i+1 complete -> next chunk's stage ready
            __syncthreads();
        }
    }

    // epilogue: out = acc + sum_e gate[b,e] * beta[e,u]
#pragma unroll
    for (int mm = 0; mm < 2; ++mm) {
        const int row0 = warp_m * 32 + mm * 16 + g;
        const int row1 = row0 + 8;
        float ge0[E_DIM], ge1[E_DIM];
#pragma unroll
        for (int e = 0; e < E_DIM; ++e) {
            ge0[e] = gate_sh[row0 * E_DIM + e];
            ge1[e] = gate_sh[row1 * E_DIM + e];
        }
#pragma unroll
        for (int nn = 0; nn < 4; ++nn) {
            const int c = warp_n * 32 + nn * 8 + 2 * tg;
            float b00 = 0.f, b01 = 0.f, b10 = 0.f, b11 = 0.f;
#pragma unroll
            for (int e = 0; e < E_DIM; ++e) {
                const float be0 = beta_sh[e * BN + c];
                const float be1 = beta_sh[e * BN + c + 1];
                b00 += ge0[e] * be0;  b01 += ge0[e] * be1;
                b10 += ge1[e] * be0;  b11 += ge1[e] * be1;
            }
            float2 v0 = make_float2(acc[mm][nn][0] + b00, acc[mm][nn][1] + b01);
            float2 v1 = make_float2(acc[mm][nn][2] + b10, acc[mm][nn][3] + b11);
            *reinterpret_cast<float2*>(out + (size_t)(mbase + row0) * U_DIM + ubase + c) = v0;
            *reinterpret_cast<float2*>(out + (size_t)(mbase + row1) * U_DIM + ubase + c) = v1;
        }
    }
}

extern "C" void kernel_launch(void* const* d_in, const int* in_sizes, int n_in,
                              void* d_out, int out_size)
{
    const float* x     = (const float*)d_in[0];
    const float* gate  = (const float*)d_in[1];
    const float* alpha = (const float*)d_in[2];
    const float* beta  = (const float*)d_in[3];
    float* out         = (float*)d_out;

    round_alpha<<<(E_DIM * IN_DIM * U_DIM) / (256 * 4), 256>>>(alpha);

    static bool attr_set = false;
    if (!attr_set) {
        cudaFuncSetAttribute(moe_kernel, cudaFuncAttributeMaxDynamicSharedMemorySize, SMEM_BYTES);
        attr_set = true;
    }
    moe_kernel<<<dim3(U_DIM / BN, B_DIM / BM), THREADS, SMEM_BYTES>>>(x, gate, beta, out);
}

// round 10
// speedup vs baseline: 1.6804x; 1.0353x over previous
#include <cuda_runtime.h>
#include <cstdint>

#define B_DIM  32768
#define IN_DIM 1024
#define U_DIM  1024
#define E_DIM  8

#define BM 128
#define BN 128
#define BK 32
#define THREADS 512
#define NITER 256               // 32 kc * 8 e
#define NBSTAGE 6

// smem layout in floats
#define AROW 36                 // 32 + 4 pad: A frag LDS conflict-free
#define BROW 136                // 128 + 8 pad: B frag LDS conflict-free
#define A_STAGE_F (BM * AROW)   // 4608
#define B_STAGE_F (32 * BROW)   // 4352
#define OFF_GATE 0              // 128*8 = 1024
#define OFF_BETA 1024           // 8*128 = 1024
#define OFF_A    2048
#define OFF_B    (OFF_A + 2 * A_STAGE_F)              // 11264
#define SMEM_FLOATS (OFF_B + NBSTAGE * B_STAGE_F)     // 37376
#define SMEM_BYTES (SMEM_FLOATS * 4)                  // 149504

__device__ float g_alphaR[(size_t)E_DIM * IN_DIM * U_DIM];   // rna-rounded alpha

__device__ __forceinline__ uint32_t smem_u32(const void* p) {
    uint32_t a;
    asm("{ .reg .u64 t; cvta.to.shared.u64 t, %1; cvt.u32.u64 %0, t; }" : "=r"(a) : "l"(p));
    return a;
}
__device__ __forceinline__ uint32_t f2tf32(float f) {
    uint32_t r; asm("cvt.rna.tf32.f32 %0, %1;" : "=r"(r) : "f"(f)); return r;
}
__device__ __forceinline__ void cp16(uint32_t dst, const void* src) {
    asm volatile("cp.async.cg.shared.global [%0], [%1], 16;" :: "r"(dst), "l"(src));
}
#define CP_COMMIT() asm volatile("cp.async.commit_group;" ::: "memory")
#define CP_WAIT2()  asm volatile("cp.async.wait_group 2;" ::: "memory")

__device__ __forceinline__ void mma_tf32(float c[4],
                                         uint32_t a0, uint32_t a1, uint32_t a2, uint32_t a3,
                                         uint32_t b0, uint32_t b1) {
    asm volatile(
        "mma.sync.aligned.m16n8k8.row.col.f32.tf32.tf32.f32 "
        "{%0,%1,%2,%3}, {%4,%5,%6,%7}, {%8,%9}, {%0,%1,%2,%3};\n"
        : "+f"(c[0]), "+f"(c[1]), "+f"(c[2]), "+f"(c[3])
        : "r"(a0), "r"(a1), "r"(a2), "r"(a3), "r"(b0), "r"(b1));
}

// ---------------- prologue: rna-round alpha into scratch ----------------
__global__ void round_alpha(const float* __restrict__ alpha) {
    const size_t idx = ((size_t)blockIdx.x * 256 + threadIdx.x) * 4;
    float4 v = *reinterpret_cast<const float4*>(alpha + idx);
    float4 r;
    r.x = __uint_as_float(f2tf32(v.x));
    r.y = __uint_as_float(f2tf32(v.y));
    r.z = __uint_as_float(f2tf32(v.z));
    r.w = __uint_as_float(f2tf32(v.w));
    *reinterpret_cast<float4*>(g_alphaR + idx) = r;
}

// ---------------- main kernel ----------------
__global__ __launch_bounds__(THREADS, 1)
void moe_kernel(const float* __restrict__ x,
                const float* __restrict__ gate,
                const float* __restrict__ beta,
                float* __restrict__ out)
{
    extern __shared__ float sm[];
    float* gate_sh = sm + OFF_GATE;
    float* beta_sh = sm + OFF_BETA;
    const uint32_t sbase = smem_u32(sm);
    const uint32_t aA = sbase + OFF_A * 4;
    const uint32_t aB = sbase + OFF_B * 4;

    const int tid  = threadIdx.x;
    const int wid  = tid >> 5;
    const int lane = tid & 31;
    const int warp_m = wid & 3;       // 4-way over m (32 rows each)
    const int warp_n = wid >> 2;      // 4-way over n (32 cols each)
    const int g  = lane >> 2;
    const int tg = lane & 3;
    const int mbase = blockIdx.y * BM;
    const int ubase = blockIdx.x * BN;

    // stage gate (128x8) and beta (8x128) tiles
    if (tid < 256) {
        const int idx = tid * 4;
        float4 gv = *reinterpret_cast<const float4*>(gate + (size_t)mbase * E_DIM + idx);
        *reinterpret_cast<float4*>(gate_sh + idx) = gv;
    } else {
        const int idx = (tid - 256) * 4;
        const int e = idx >> 7, c = idx & 127;
        float4 bv = *reinterpret_cast<const float4*>(beta + (size_t)e * U_DIM + ubase + c);
        *reinterpret_cast<float4*>(beta_sh + idx) = bv;
    }

    // cp.async geometry (2x cp16 per thread per tile)
    const int a_row = tid >> 2;           // 0..127
    const int a_kq  = (tid & 3) * 8;      // k offset, 8 floats
    const int b_k   = tid >> 4;           // 0..31
    const int b_cq  = (tid & 15) * 8;     // col offset, 8 floats

    auto issueA = [&](int kc, int st) {
        const uint32_t dst = aA + st * (A_STAGE_F * 4) + a_row * (AROW * 4) + a_kq * 4;
        const float* src = x + (size_t)(mbase + a_row) * IN_DIM + kc * BK + a_kq;
        cp16(dst,      src);
        cp16(dst + 16, src + 4);
    };
    auto issueB = [&](int it, int st) {
        const int kc = it >> 3, e = it & 7;
        const uint32_t dst = aB + st * (B_STAGE_F * 4) + b_k * (BROW * 4) + b_cq * 4;
        const float* src = g_alphaR + (size_t)e * (IN_DIM * U_DIM)
                         + (size_t)(kc * BK + b_k) * U_DIM + ubase + b_cq;
        cp16(dst,      src);
        cp16(dst + 16, src + 4);
    };

    float Ar[4][2][4];     // [ks][mm][frag] unscaled x fragments, cached per kc
    float acc[2][4][4];    // [mm][nn][frag]
#pragma unroll
    for (int i = 0; i < 2; ++i)
#pragma unroll
        for (int j = 0; j < 4; ++j)
#pragma unroll
            for (int k = 0; k < 4; ++k) acc[i][j][k] = 0.f;

    // compute one (kc, e) chunk from B stage st
    auto compute = [&](int kc, int e, int st) {
        const float* Bs = sm + OFF_B + st * B_STAGE_F;

        if (e == 0) {
            const float* As = sm + OFF_A + (kc & 1) * A_STAGE_F;
#pragma unroll
            for (int ks = 0; ks < 4; ++ks)
#pragma unroll
                for (int mm = 0; mm < 2; ++mm) {
                    const int r0 = warp_m * 32 + mm * 16 + g;
                    const int k0 = ks * 8 + tg;
                    Ar[ks][mm][0] = As[r0 * AROW + k0];
                    Ar[ks][mm][1] = As[(r0 + 8) * AROW + k0];
                    Ar[ks][mm][2] = As[r0 * AROW + k0 + 4];
                    Ar[ks][mm][3] = As[(r0 + 8) * AROW + k0 + 4];
                }
        }

        float gs0[2], gs1[2];
#pragma unroll
        for (int mm = 0; mm < 2; ++mm) {
            const int r0 = warp_m * 32 + mm * 16 + g;
            gs0[mm] = gate_sh[r0 * E_DIM + e];
            gs1[mm] = gate_sh[(r0 + 8) * E_DIM + e];
        }

#pragma unroll
        for (int ks = 0; ks < 4; ++ks) {
            uint32_t b0[4], b1[4];
#pragma unroll
            for (int nn = 0; nn < 4; ++nn) {
                const int n = warp_n * 32 + nn * 8 + g;
                const int k = ks * 8 + tg;
                b0[nn] = __float_as_uint(Bs[k * BROW + n]);
                b1[nn] = __float_as_uint(Bs[(k + 4) * BROW + n]);
            }
#pragma unroll
            for (int mm = 0; mm < 2; ++mm) {
                const uint32_t a0 = __float_as_uint(Ar[ks][mm][0] * gs0[mm]);
                const uint32_t a1 = __float_as_uint(Ar[ks][mm][1] * gs1[mm]);
                const uint32_t a2 = __float_as_uint(Ar[ks][mm][2] * gs0[mm]);
                const uint32_t a3 = __float_as_uint(Ar[ks][mm][3] * gs1[mm]);
#pragma unroll
                for (int nn = 0; nn < 4; ++nn)
                    mma_tf32(acc[mm][nn], a0, a1, a2, a3, b0[nn], b1[nn]);
            }
        }
    };

    // prologue: chunks 0..3 into B stages 0..3, one group each (A kc=0 rides with group 0)
    issueA(0, 0); issueB(0, 0); CP_COMMIT();
    issueB(1, 1);               CP_COMMIT();
    issueB(2, 2);               CP_COMMIT();
    issueB(3, 3);               CP_COMMIT();
    CP_WAIT2();                 // groups 0,1 complete
    __syncthreads();

    int s_c = 0;   // stage of chunk i0
    int s_w = 4;   // stage of chunk i0+4

    for (int kc = 0; kc < 32; ++kc) {
#pragma unroll
        for (int ep = 0; ep < 4; ++ep) {
            const int i0 = kc * 8 + 2 * ep;
            // first issue: chunk i0+4 (plus A for kc+1 when i0+4 crosses into it)
            if (i0 + 4 < NITER) {
                issueB(i0 + 4, s_w);
                if (ep == 2) issueA(kc + 1, (kc + 1) & 1);
            }
            CP_COMMIT();

            compute(kc, 2 * ep, s_c);

            // second issue: chunk i0+5
            if (i0 + 5 < NITER) issueB(i0 + 5, s_w + 1 == NBSTAGE ? 0 : s_w + 1);
            CP_COMMIT();

            compute(kc, 2 * ep + 1, s_c + 1 == NBSTAGE ? 0 : s_c + 1);

            CP_WAIT2();          // groups up through chunk i0+3 complete
            __syncthreads();

            s_c += 2; if (s_c >= NBSTAGE) s_c -= NBSTAGE;
            s_w += 2; if (s_w >= NBSTAGE) s_w -= NBSTAGE;
        }
    }

    // epilogue: out = acc + sum_e gate[b,e] * beta[e,u]
#pragma unroll
    for (int mm = 0; mm < 2; ++mm) {
        const int row0 = warp_m * 32 + mm * 16 + g;
        const int row1 = row0 + 8;
        float ge0[E_DIM], ge1[E_DIM];
#pragma unroll
        for (int e = 0; e < E_DIM; ++e) {
            ge0[e] = gate_sh[row0 * E_DIM + e];
            ge1[e] = gate_sh[row1 * E_DIM + e];
        }
#pragma unroll
        for (int nn = 0; nn < 4; ++nn) {
            const int c = warp_n * 32 + nn * 8 + 2 * tg;
            float b00 = 0.f, b01 = 0.f, b10 = 0.f, b11 = 0.f;
#pragma unroll
            for (int e = 0; e < E_DIM; ++e) {
                const float be0 = beta_sh[e * BN + c];
                const float be1 = beta_sh[e * BN + c + 1];
                b00 += ge0[e] * be0;  b01 += ge0[e] * be1;
                b10 += ge1[e] * be0;  b11 += ge1[e] * be1;
            }
            float2 v0 = make_float2(acc[mm][nn][0] + b00, acc[mm][nn][1] + b01);
            float2 v1 = make_float2(acc[mm][nn][2] + b10, acc[mm][nn][3] + b11);
            *reinterpret_cast<float2*>(out + (size_t)(mbase + row0) * U_DIM + ubase + c) = v0;
            *reinterpret_cast<float2*>(out + (size_t)(mbase + row1) * U_DIM + ubase + c) = v1;
        }
    }
}

extern "C" void kernel_launch(void* const* d_in, const int* in_sizes, int n_in,
                              void* d_out, int out_size)
{
    const float* x     = (const float*)d_in[0];
    const float* gate  = (const float*)d_in[1];
    const float* alpha = (const float*)d_in[2];
    const float* beta  = (const float*)d_in[3];
    float* out         = (float*)d_out;

    round_alpha<<<(E_DIM * IN_DIM * U_DIM) / (256 * 4), 256>>>(alpha);

    static bool attr_set = false;
    if (!attr_set) {
        cudaFuncSetAttribute(moe_kernel, cudaFuncAttributeMaxDynamicSharedMemorySize, SMEM_BYTES);
        attr_set = true;
    }
    moe_kernel<<<dim3(U_DIM / BN, B_DIM / BM), THREADS, SMEM_BYTES>>>(x, gate, beta, out);
}

// round 17
// speedup vs baseline: 1.7159x; 1.0211x over previous
#include <cuda_runtime.h>
#include <cstdint>

#define B_DIM  32768
#define IN_DIM 1024
#define U_DIM  1024
#define E_DIM  8

#define BM 128
#define BN 128
#define BK 32
#define THREADS 512
#define NITER 256               // 32 kc * 8 e
#define NBSTAGE 8

// smem layout in floats
#define AROW 36                 // 32 + 4 pad: A frag LDS conflict-free
#define BROW 136                // 128 + 8 pad: B frag LDS conflict-free
#define A_STAGE_F (BM * AROW)   // 4608
#define B_STAGE_F (32 * BROW)   // 4352
#define OFF_GATE 0              // 128*8 = 1024
#define OFF_BETA 1024           // 8*128 = 1024
#define OFF_BAR  2048           // 16 mbarriers x 8B = 128B = 32 floats
#define OFF_A    2080
#define OFF_B    (OFF_A + 2 * A_STAGE_F)              // 11296
#define SMEM_FLOATS (OFF_B + NBSTAGE * B_STAGE_F)     // 46112
#define SMEM_BYTES (SMEM_FLOATS * 4)                  // 184448

__device__ float g_alphaR[(size_t)E_DIM * IN_DIM * U_DIM];   // rna-rounded alpha

__device__ __forceinline__ uint32_t smem_u32(const void* p) {
    uint32_t a;
    asm("{ .reg .u64 t; cvta.to.shared.u64 t, %1; cvt.u32.u64 %0, t; }" : "=r"(a) : "l"(p));
    return a;
}
__device__ __forceinline__ uint32_t f2tf32(float f) {
    uint32_t r; asm("cvt.rna.tf32.f32 %0, %1;" : "=r"(r) : "f"(f)); return r;
}
__device__ __forceinline__ void cp16(uint32_t dst, const void* src) {
    asm volatile("cp.async.cg.shared.global [%0], [%1], 16;" :: "r"(dst), "l"(src));
}

// ---- mbarrier helpers ----
#define MBAR_INIT(a, n) asm volatile("mbarrier.init.shared.b64 [%0], %1;" :: "r"(a), "r"(n) : "memory")
#define MBAR_ARRIVE(a)  asm volatile("mbarrier.arrive.shared.b64 _, [%0];" :: "r"(a) : "memory")
// arrive on completion of this thread's prior cp.asyncs (no extra expected-count)
#define CP_MBAR_ARRIVE(a) asm volatile("cp.async.mbarrier.arrive.noinc.shared.b64 [%0];" :: "r"(a) : "memory")
__device__ __forceinline__ void mbar_wait(uint32_t addr, uint32_t parity) {
    asm volatile(
        "{\n\t.reg .pred P;\n"
        "W%=:\n\t"
        "mbarrier.try_wait.parity.acquire.cta.shared::cta.b64 P, [%0], %1, 0x989680;\n\t"
        "@P bra.uni D%=;\n\t"
        "bra.uni W%=;\n"
        "D%=:\n\t}"
        :: "r"(addr), "r"(parity) : "memory");
}

__device__ __forceinline__ void mma_tf32(float c[4],
                                         uint32_t a0, uint32_t a1, uint32_t a2, uint32_t a3,
                                         uint32_t b0, uint32_t b1) {
    asm volatile(
        "mma.sync.aligned.m16n8k8.row.col.f32.tf32.tf32.f32 "
        "{%0,%1,%2,%3}, {%4,%5,%6,%7}, {%8,%9}, {%0,%1,%2,%3};\n"
        : "+f"(c[0]), "+f"(c[1]), "+f"(c[2]), "+f"(c[3])
        : "r"(a0), "r"(a1), "r"(a2), "r"(a3), "r"(b0), "r"(b1));
}

// ---------------- prologue: rna-round alpha into scratch ----------------
__global__ void round_alpha(const float* __restrict__ alpha) {
    const size_t idx = ((size_t)blockIdx.x * 256 + threadIdx.x) * 4;
    float4 v = *reinterpret_cast<const float4*>(alpha + idx);
    float4 r;
    r.x = __uint_as_float(f2tf32(v.x));
    r.y = __uint_as_float(f2tf32(v.y));
    r.z = __uint_as_float(f2tf32(v.z));
    r.w = __uint_as_float(f2tf32(v.w));
    *reinterpret_cast<float4*>(g_alphaR + idx) = r;
}

// ---------------- main kernel ----------------
__global__ __launch_bounds__(THREADS, 1)
void moe_kernel(const float* __restrict__ x,
                const float* __restrict__ gate,
                const float* __restrict__ beta,
                float* __restrict__ out)
{
    extern __shared__ float sm[];
    float* gate_sh = sm + OFF_GATE;
    float* beta_sh = sm + OFF_BETA;
    const uint32_t sbase = smem_u32(sm);
    const uint32_t aBAR = sbase + OFF_BAR * 4;
    const uint32_t aA = sbase + OFF_A * 4;
    const uint32_t aB = sbase + OFF_B * 4;

    const int tid  = threadIdx.x;
    const int wid  = tid >> 5;
    const int lane = tid & 31;
    const int warp_m = wid & 3;       // 4-way over m (32 rows each)
    const int warp_n = wid >> 2;      // 4-way over n (32 cols each)
    const int g  = lane >> 2;
    const int tg = lane & 3;
    const int mbase = blockIdx.y * BM;
    const int ubase = blockIdx.x * BN;

    // full[s] = aBAR + s*16, empty[s] = aBAR + s*16 + 8
    if (tid == 0) {
#pragma unroll
        for (int s = 0; s < NBSTAGE; ++s) {
            MBAR_INIT(aBAR + s * 16,     THREADS);
            MBAR_INIT(aBAR + s * 16 + 8, THREADS);
        }
    }

    // stage gate (128x8) and beta (8x128) tiles
    if (tid < 256) {
        const int idx = tid * 4;
        float4 gv = *reinterpret_cast<const float4*>(gate + (size_t)mbase * E_DIM + idx);
        *reinterpret_cast<float4*>(gate_sh + idx) = gv;
    } else {
        const int idx = (tid - 256) * 4;
        const int e = idx >> 7, c = idx & 127;
        float4 bv = *reinterpret_cast<const float4*>(beta + (size_t)e * U_DIM + ubase + c);
        *reinterpret_cast<float4*>(beta_sh + idx) = bv;
    }
    __syncthreads();   // mbarrier init + gate/beta visible

    // cp.async geometry (2x cp16 per thread per tile)
    const int a_row = tid >> 2;           // 0..127
    const int a_kq  = (tid & 3) * 8;      // k offset, 8 floats
    const int b_k   = tid >> 4;           // 0..31
    const int b_cq  = (tid & 15) * 8;     // col offset, 8 floats

    auto issueA = [&](int kc, int st) {
        const uint32_t dst = aA + st * (A_STAGE_F * 4) + a_row * (AROW * 4) + a_kq * 4;
        const float* src = x + (size_t)(mbase + a_row) * IN_DIM + kc * BK + a_kq;
        cp16(dst,      src);
        cp16(dst + 16, src + 4);
    };
    auto issueB = [&](int it, int st) {
        const int kc = it >> 3, e = it & 7;
        const uint32_t dst = aB + st * (B_STAGE_F * 4) + b_k * (BROW * 4) + b_cq * 4;
        const float* src = g_alphaR + (size_t)e * (IN_DIM * U_DIM)
                         + (size_t)(kc * BK + b_k) * U_DIM + ubase + b_cq;
        cp16(dst,      src);
        cp16(dst + 16, src + 4);
    };

    float Ar[4][2][4];     // [ks][mm][frag] unscaled x fragments, cached per kc
    float acc[2][4][4];    // [mm][nn][frag]
#pragma unroll
    for (int i = 0; i < 2; ++i)
#pragma unroll
        for (int j = 0; j < 4; ++j)
#pragma unroll
            for (int k = 0; k < 4; ++k) acc[i][j][k] = 0.f;

    // compute one (kc, e) chunk from B stage st
    auto compute = [&](int kc, int e, int st) {
        const float* Bs = sm + OFF_B + st * B_STAGE_F;

        if (e == 0) {
            const float* As = sm + OFF_A + (kc & 1) * A_STAGE_F;
#pragma unroll
            for (int ks = 0; ks < 4; ++ks)
#pragma unroll
                for (int mm = 0; mm < 2; ++mm) {
                    const int r0 = warp_m * 32 + mm * 16 + g;
                    const int k0 = ks * 8 + tg;
                    Ar[ks][mm][0] = As[r0 * AROW + k0];
                    Ar[ks][mm][1] = As[(r0 + 8) * AROW + k0];
                    Ar[ks][mm][2] = As[r0 * AROW + k0 + 4];
                    Ar[ks][mm][3] = As[(r0 + 8) * AROW + k0 + 4];
                }
        }

        float gs0[2], gs1[2];
#pragma unroll
        for (int mm = 0; mm < 2; ++mm) {
            const int r0 = warp_m * 32 + mm * 16 + g;
            gs0[mm] = gate_sh[r0 * E_DIM + e];
            gs1[mm] = gate_sh[(r0 + 8) * E_DIM + e];
        }

#pragma unroll
        for (int ks = 0; ks < 4; ++ks) {
            uint32_t b0[4], b1[4];
#pragma unroll
            for (int nn = 0; nn < 4; ++nn) {
                const int n = warp_n * 32 + nn * 8 + g;
                const int k = ks * 8 + tg;
                b0[nn] = __float_as_uint(Bs[k * BROW + n]);
                b1[nn] = __float_as_uint(Bs[(k + 4) * BROW + n]);
            }
#pragma unroll
            for (int mm = 0; mm < 2; ++mm) {
                const uint32_t a0 = __float_as_uint(Ar[ks][mm][0] * gs0[mm]);
                const uint32_t a1 = __float_as_uint(Ar[ks][mm][1] * gs1[mm]);
                const uint32_t a2 = __float_as_uint(Ar[ks][mm][2] * gs0[mm]);
                const uint32_t a3 = __float_as_uint(Ar[ks][mm][3] * gs1[mm]);
#pragma unroll
                for (int nn = 0; nn < 4; ++nn)
                    mma_tf32(acc[mm][nn], a0, a1, a2, a3, b0[nn], b1[nn]);
            }
        }
    };

    // pipeline cursors
    int ps = 0, pp = 1;    // producer stage & empty-wait parity (1 -> first pass immediate)
    int cs = 0, cf = 0;    // consumer stage & full-wait parity

    auto produce = [&](int p) {
        mbar_wait(aBAR + ps * 16 + 8, pp);        // wait empty[ps]
        issueB(p, ps);
        if ((p & 7) == 0) issueA(p >> 3, (p >> 3) & 1);
        CP_MBAR_ARRIVE(aBAR + ps * 16);           // full[ps] on copy completion
        if (++ps == NBSTAGE) { ps = 0; pp ^= 1; }
    };

    // prologue: fill 7 stages ahead
#pragma unroll
    for (int p = 0; p < NBSTAGE - 1; ++p) produce(p);

    for (int c = 0; c < NITER; ++c) {
        if (c + NBSTAGE - 1 < NITER) produce(c + NBSTAGE - 1);
        mbar_wait(aBAR + cs * 16, cf);            // wait full[cs]
        compute(c >> 3, c & 7, cs);
        MBAR_ARRIVE(aBAR + cs * 16 + 8);          // arrive empty[cs]
        if (++cs == NBSTAGE) { cs = 0; cf ^= 1; }
    }

    // epilogue: out = acc + sum_e gate[b,e] * beta[e,u]
#pragma unroll
    for (int mm = 0; mm < 2; ++mm) {
        const int row0 = warp_m * 32 + mm * 16 + g;
        const int row1 = row0 + 8;
        float ge0[E_DIM], ge1[E_DIM];
#pragma unroll
        for (int e = 0; e < E_DIM; ++e) {
            ge0[e] = gate_sh[row0 * E_DIM + e];
            ge1[e] = gate_sh[row1 * E_DIM + e];
        }
#pragma unroll
        for (int nn = 0; nn < 4; ++nn) {
            const int c = warp_n * 32 + nn * 8 + 2 * tg;
            float b00 = 0.f, b01 = 0.f, b10 = 0.f, b11 = 0.f;
#pragma unroll
            for (int e = 0; e < E_DIM; ++e) {
                const float be0 = beta_sh[e * BN + c];
                const float be1 = beta_sh[e * BN + c + 1];
                b00 += ge0[e] * be0;  b01 += ge0[e] * be1;
                b10 += ge1[e] * be0;  b11 += ge1[e] * be1;
            }
            float2 v0 = make_float2(acc[mm][nn][0] + b00, acc[mm][nn][1] + b01);
            float2 v1 = make_float2(acc[mm][nn][2] + b10, acc[mm][nn][3] + b11);
            *reinterpret_cast<float2*>(out + (size_t)(mbase + row0) * U_DIM + ubase + c) = v0;
            *reinterpret_cast<float2*>(out + (size_t)(mbase + row1) * U_DIM + ubase + c) = v1;
        }
    }
}

extern "C" void kernel_launch(void* const* d_in, const int* in_sizes, int n_in,
                              void* d_out, int out_size)
{
    const float* x     = (const float*)d_in[0];
    const float* gate  = (const float*)d_in[1];
    const float* alpha = (const float*)d_in[2];
    const float* beta  = (const float*)d_in[3];
    float* out         = (float*)d_out;

    round_alpha<<<(E_DIM * IN_DIM * U_DIM) / (256 * 4), 256>>>(alpha);

    static bool attr_set = false;
    if (!attr_set) {
        cudaFuncSetAttribute(moe_kernel, cudaFuncAttributeMaxDynamicSharedMemorySize, SMEM_BYTES);
        attr_set = true;
    }
    moe_kernel<<<dim3(U_DIM / BN, B_DIM / BM), THREADS, SMEM_BYTES>>>(x, gate, beta, out);
}